// round 12
// baseline (speedup 1.0000x reference)
#include <cuda_runtime.h>
#include <cstdint>
#include <cstddef>

// DynamicFC: out[b,o,h,w] = sum_i W[b,o,i] * X[b,i,h,w] + bias[b,o]
// B=64, Cin=Cout=512, HW=784, fp32.  Per-batch GEMM C[512,784] = W @ X + bias.
//
// R10: R9 (128x112x32, 256 thr, warp 32x56, 3-stage cp.async, 2 CTAs/SM,
// one barrier/stage) + WARP PHASE SKEW: the two warps sharing an SMSP
// (wid, wid+4) traverse the 4 ks-slices starting at opposite offsets
// (skew 0 vs 2), so one warp's LDS/cvt phase overlaps the other's MMA burst
// instead of serializing on the same pipe. Pure k-reordering; same math.

#define COUT 512
#define CIN  512
#define HW   784

#define BM 128
#define BN 112
#define BK 32
#define NSTAGES 3
#define NITERS (CIN / BK)     // 16

#define AST 36                // A smem row stride (floats): banks 4g+tg, CF
#define BST 120               // B smem row stride (floats): banks 24tg+8j+g, CF
#define A_STAGE (BM * AST)    // 4608 floats
#define B_STAGE (BK * BST)    // 3840 floats
#define SMEM_FLOATS (NSTAGES * (A_STAGE + B_STAGE))   // 25344 floats = 101376 B

__device__ __forceinline__ uint32_t smem_u32(const void* p) {
    uint32_t a;
    asm("{ .reg .u64 t; cvta.to.shared.u64 t, %1; cvt.u32.u64 %0, t; }"
        : "=r"(a) : "l"(p));
    return a;
}
__device__ __forceinline__ uint32_t f2tf32(float x) {
    uint32_t u;
    asm("cvt.rna.tf32.f32 %0, %1;" : "=r"(u) : "f"(x));
    return u;
}
__device__ __forceinline__ void cpasync16(uint32_t s, const void* g) {
    asm volatile("cp.async.cg.shared.global [%0], [%1], 16;" :: "r"(s), "l"(g));
}
__device__ __forceinline__ void mma1688(float* c, const uint32_t* a, const uint32_t* b) {
    asm volatile(
        "mma.sync.aligned.m16n8k8.row.col.f32.tf32.tf32.f32 "
        "{%0,%1,%2,%3}, {%4,%5,%6,%7}, {%8,%9}, {%0,%1,%2,%3};"
        : "+f"(c[0]), "+f"(c[1]), "+f"(c[2]), "+f"(c[3])
        : "r"(a[0]), "r"(a[1]), "r"(a[2]), "r"(a[3]), "r"(b[0]), "r"(b[1]));
}

__device__ __forceinline__ void fill_stage(int st, int tid, uint32_t sb,
                                           const float* __restrict__ Wb,
                                           const float* __restrict__ Xb, int n0) {
    const int buf = st % NSTAGES;
    const uint32_t aB = sb + buf * (A_STAGE * 4);
    const uint32_t bB = sb + NSTAGES * (A_STAGE * 4) + buf * (B_STAGE * 4);
    const int k0 = st * BK;
    // A: 128 rows x 32 k = 1024 float4 chunks (4/thread), coalesced
#pragma unroll
    for (int i = 0; i < 4; i++) {
        const int c   = tid + i * 256;
        const int row = c >> 3;
        const int kb  = c & 7;
        cpasync16(aB + (row * AST + kb * 4) * 4,
                  Wb + (size_t)row * CIN + k0 + kb * 4);
    }
    // B: 32 k-rows x 112 cols = 896 float4 chunks, coalesced
#pragma unroll
    for (int i = 0; i < 4; i++) {
        const int c = tid + i * 256;
        if (c < 896) {
            const int row = c / 28;
            const int ch  = c - row * 28;
            cpasync16(bB + (row * BST + ch * 4) * 4,
                      Xb + (size_t)(k0 + row) * HW + n0 + ch * 4);
        }
    }
    asm volatile("cp.async.commit_group;" ::: "memory");
}

__global__ __launch_bounds__(256, 2)
void dynfc_tf32_kernel(const float* __restrict__ input,
                       const float* __restrict__ weight,
                       const float* __restrict__ bias,
                       float* __restrict__ out)
{
    extern __shared__ float smem[];
    const uint32_t sb = smem_u32(smem);

    const int tid  = threadIdx.x;
    const int wid  = tid >> 5;
    const int lane = tid & 31;
    const int g    = lane >> 2;      // 0..7
    const int tg   = lane & 3;       // 0..3
    const int wm   = wid >> 1;       // 0..3 (m warps, 32 rows)
    const int wn   = wid & 1;        // 0..1 (n warps, 56 cols)
    // Same-SMSP warps (wid, wid+4) get opposite ks phases.
    const int skew = (wid & 4) ? 2 : 0;

    const int b  = blockIdx.z;
    const int m0 = blockIdx.y * BM;
    const int n0 = blockIdx.x * BN;

    const float* Wb = weight + ((size_t)b * COUT + m0) * CIN;
    const float* Xb = input  + (size_t)b * CIN * HW;

    // Accumulators: 2 m-atoms x 7 n-atoms x 4, bias folded into init.
    float acc[2][7][4];
#pragma unroll
    for (int am = 0; am < 2; am++) {
        const int r0 = m0 + wm * 32 + am * 16 + g;
        const float bv0 = bias[b * COUT + r0];
        const float bv1 = bias[b * COUT + r0 + 8];
#pragma unroll
        for (int j = 0; j < 7; j++) {
            acc[am][j][0] = bv0; acc[am][j][1] = bv0;
            acc[am][j][2] = bv1; acc[am][j][3] = bv1;
        }
    }

    // Prologue: fill stages 0, 1.
    fill_stage(0, tid, sb, Wb, Xb, n0);
    fill_stage(1, tid, sb, Wb, Xb, n0);

    for (int s = 0; s < NITERS; s++) {
        const int buf = s % NSTAGES;
        if (s < NITERS - 1) {
            asm volatile("cp.async.wait_group 1;" ::: "memory");
        } else {
            asm volatile("cp.async.wait_group 0;" ::: "memory");
        }
        __syncthreads();           // single barrier per stage
        if (s + 2 < NITERS) fill_stage(s + 2, tid, sb, Wb, Xb, n0);

        const float* Aw = smem + buf * A_STAGE + (wm * 32) * AST;
        const float* Bw = smem + NSTAGES * A_STAGE + buf * B_STAGE + wn * 56;

#pragma unroll
        for (int ks = 0; ks < BK / 8; ks++) {
            const int kk = (ks + skew) & 3;     // phase-skewed slice order
            // B fragments first: they feed all 14 MMAs.
            uint32_t bfrag[7][2];
#pragma unroll
            for (int j = 0; j < 7; j++) {
                const float* bp = Bw + (kk * 8 + tg) * BST + j * 8 + g;
                bfrag[j][0] = f2tf32(bp[0]);
                bfrag[j][1] = f2tf32(bp[4 * BST]);
            }
            uint32_t afrag[2][4];
#pragma unroll
            for (int am = 0; am < 2; am++) {
                const float* ap = Aw + (am * 16 + g) * AST + kk * 8 + tg;
                afrag[am][0] = f2tf32(ap[0]);
                afrag[am][1] = f2tf32(ap[8 * AST]);
                afrag[am][2] = f2tf32(ap[4]);
                afrag[am][3] = f2tf32(ap[8 * AST + 4]);
            }
#pragma unroll
            for (int am = 0; am < 2; am++)
#pragma unroll
                for (int j = 0; j < 7; j++)
                    mma1688(acc[am][j], afrag[am], bfrag[j]);
        }
    }

    // Epilogue: direct float2 stores (cols 2tg, 2tg+1 contiguous).
    float* Cb = out + (size_t)b * COUT * HW;
#pragma unroll
    for (int am = 0; am < 2; am++) {
        const int r0 = m0 + wm * 32 + am * 16 + g;
#pragma unroll
        for (int j = 0; j < 7; j++) {
            const int col = n0 + wn * 56 + j * 8 + 2 * tg;
            float2 v0 = make_float2(acc[am][j][0], acc[am][j][1]);
            float2 v1 = make_float2(acc[am][j][2], acc[am][j][3]);
            *reinterpret_cast<float2*>(Cb + (size_t)r0 * HW + col)       = v0;
            *reinterpret_cast<float2*>(Cb + (size_t)(r0 + 8) * HW + col) = v1;
        }
    }
}

extern "C" void kernel_launch(void* const* d_in, const int* in_sizes, int n_in,
                              void* d_out, int out_size)
{
    const float* input  = (const float*)d_in[0];  // (64, 512, 28, 28)
    const float* weight = (const float*)d_in[1];  // (64, 512, 512, 1, 1)
    const float* bias   = (const float*)d_in[2];  // (64, 512)
    float* out = (float*)d_out;

    cudaFuncSetAttribute(dynfc_tf32_kernel,
                         cudaFuncAttributeMaxDynamicSharedMemorySize,
                         SMEM_FLOATS * 4);
    dim3 grid(HW / BN, COUT / BM, 64);            // (7, 4, 64)
    dynfc_tf32_kernel<<<grid, 256, SMEM_FLOATS * 4>>>(input, weight, bias, out);
}

// round 13
// speedup vs baseline: 1.0467x; 1.0467x over previous
#include <cuda_runtime.h>
#include <cstdint>
#include <cstddef>

// DynamicFC: out[b,o,h,w] = sum_i W[b,o,i] * X[b,i,h,w] + bias[b,o]
// B=64, Cin=Cout=512, HW=784, fp32.  Per-batch GEMM C[512,784] = W @ X + bias.
//
// R11: R9 (best: 128x112x32, 256 thr, warp 32x56, 3-stage cp.async,
// 2 CTAs/SM, one barrier/stage) + A fragments via ldmatrix.m8n8.x4.b16:
// the 16x8 tf32 A atom viewed as four 8x8 b16 matrices gives EXACTLY the
// mma.m16n8k8 A fragment (a0=A[g][tg], a1=A[g+8][tg], a2=A[g][tg+4],
// a3=A[g+8][tg+4]) when lane L supplies row (L&15), col-offset (L>>4)*4.
// 8 LDS.32 + addr math -> 2 ldmatrix per ks. B stays scalar LDS (trans
// ldmatrix is b16-granular, unusable for tf32). Same math, same rel_err.

#define COUT 512
#define CIN  512
#define HW   784

#define BM 128
#define BN 112
#define BK 32
#define NSTAGES 3
#define NITERS (CIN / BK)     // 16

#define AST 36                // A smem row stride (floats): banks 4r+c, CF
#define BST 120               // B smem row stride (floats): banks 24tg+8j+g, CF
#define A_STAGE (BM * AST)    // 4608 floats
#define B_STAGE (BK * BST)    // 3840 floats
#define SMEM_FLOATS (NSTAGES * (A_STAGE + B_STAGE))   // 25344 floats = 101376 B

__device__ __forceinline__ uint32_t smem_u32(const void* p) {
    uint32_t a;
    asm("{ .reg .u64 t; cvta.to.shared.u64 t, %1; cvt.u32.u64 %0, t; }"
        : "=r"(a) : "l"(p));
    return a;
}
__device__ __forceinline__ uint32_t f2tf32(float x) {
    uint32_t u;
    asm("cvt.rna.tf32.f32 %0, %1;" : "=r"(u) : "f"(x));
    return u;
}
__device__ __forceinline__ void cpasync16(uint32_t s, const void* g) {
    asm volatile("cp.async.cg.shared.global [%0], [%1], 16;" :: "r"(s), "l"(g));
}
__device__ __forceinline__ void ldmatrix_x4(uint32_t& r0, uint32_t& r1,
                                            uint32_t& r2, uint32_t& r3,
                                            uint32_t addr) {
    asm volatile("ldmatrix.sync.aligned.m8n8.x4.shared.b16 {%0,%1,%2,%3}, [%4];"
                 : "=r"(r0), "=r"(r1), "=r"(r2), "=r"(r3) : "r"(addr));
}
__device__ __forceinline__ void mma1688(float* c, const uint32_t* a, const uint32_t* b) {
    asm volatile(
        "mma.sync.aligned.m16n8k8.row.col.f32.tf32.tf32.f32 "
        "{%0,%1,%2,%3}, {%4,%5,%6,%7}, {%8,%9}, {%0,%1,%2,%3};"
        : "+f"(c[0]), "+f"(c[1]), "+f"(c[2]), "+f"(c[3])
        : "r"(a[0]), "r"(a[1]), "r"(a[2]), "r"(a[3]), "r"(b[0]), "r"(b[1]));
}

__device__ __forceinline__ void fill_stage(int st, int tid, uint32_t sb,
                                           const float* __restrict__ Wb,
                                           const float* __restrict__ Xb, int n0) {
    const int buf = st % NSTAGES;
    const uint32_t aB = sb + buf * (A_STAGE * 4);
    const uint32_t bB = sb + NSTAGES * (A_STAGE * 4) + buf * (B_STAGE * 4);
    const int k0 = st * BK;
    // A: 128 rows x 32 k = 1024 float4 chunks (4/thread), coalesced
#pragma unroll
    for (int i = 0; i < 4; i++) {
        const int c   = tid + i * 256;
        const int row = c >> 3;
        const int kb  = c & 7;
        cpasync16(aB + (row * AST + kb * 4) * 4,
                  Wb + (size_t)row * CIN + k0 + kb * 4);
    }
    // B: 32 k-rows x 112 cols = 896 float4 chunks, coalesced
#pragma unroll
    for (int i = 0; i < 4; i++) {
        const int c = tid + i * 256;
        if (c < 896) {
            const int row = c / 28;
            const int ch  = c - row * 28;
            cpasync16(bB + (row * BST + ch * 4) * 4,
                      Xb + (size_t)(k0 + row) * HW + n0 + ch * 4);
        }
    }
    asm volatile("cp.async.commit_group;" ::: "memory");
}

__global__ __launch_bounds__(256, 2)
void dynfc_tf32_kernel(const float* __restrict__ input,
                       const float* __restrict__ weight,
                       const float* __restrict__ bias,
                       float* __restrict__ out)
{
    extern __shared__ float smem[];
    const uint32_t sb = smem_u32(smem);

    const int tid  = threadIdx.x;
    const int wid  = tid >> 5;
    const int lane = tid & 31;
    const int g    = lane >> 2;      // 0..7
    const int tg   = lane & 3;       // 0..3
    const int wm   = wid >> 1;       // 0..3 (m warps, 32 rows)
    const int wn   = wid & 1;        // 0..1 (n warps, 56 cols)
    // ldmatrix lane->address mapping for the A atom (16x8 tf32):
    const int rowA = lane & 15;          // matrix row within atom
    const int colA = (lane >> 4) * 4;    // tf32 column offset (0 or 4)

    const int b  = blockIdx.z;
    const int m0 = blockIdx.y * BM;
    const int n0 = blockIdx.x * BN;

    const float* Wb = weight + ((size_t)b * COUT + m0) * CIN;
    const float* Xb = input  + (size_t)b * CIN * HW;

    // Accumulators: 2 m-atoms x 7 n-atoms x 4, bias folded into init.
    float acc[2][7][4];
#pragma unroll
    for (int am = 0; am < 2; am++) {
        const int r0 = m0 + wm * 32 + am * 16 + g;
        const float bv0 = bias[b * COUT + r0];
        const float bv1 = bias[b * COUT + r0 + 8];
#pragma unroll
        for (int j = 0; j < 7; j++) {
            acc[am][j][0] = bv0; acc[am][j][1] = bv0;
            acc[am][j][2] = bv1; acc[am][j][3] = bv1;
        }
    }

    // Prologue: fill stages 0, 1.
    fill_stage(0, tid, sb, Wb, Xb, n0);
    fill_stage(1, tid, sb, Wb, Xb, n0);

    for (int s = 0; s < NITERS; s++) {
        const int buf = s % NSTAGES;
        if (s < NITERS - 1) {
            asm volatile("cp.async.wait_group 1;" ::: "memory");
        } else {
            asm volatile("cp.async.wait_group 0;" ::: "memory");
        }
        __syncthreads();           // single barrier per stage
        if (s + 2 < NITERS) fill_stage(s + 2, tid, sb, Wb, Xb, n0);

        const float* Bw = smem + NSTAGES * A_STAGE + buf * B_STAGE + wn * 56;
        // Per-thread ldmatrix base addresses (bytes) for the two A atoms.
        const uint32_t aAddr0 = sb + (buf * A_STAGE
                              + (wm * 32 + rowA) * AST + colA) * 4;
        const uint32_t aAddr1 = aAddr0 + 16 * AST * 4;

#pragma unroll
        for (int ks = 0; ks < BK / 8; ks++) {
            // B fragments first: they feed all 14 MMAs.
            uint32_t bfrag[7][2];
#pragma unroll
            for (int j = 0; j < 7; j++) {
                const float* bp = Bw + (ks * 8 + tg) * BST + j * 8 + g;
                bfrag[j][0] = f2tf32(bp[0]);
                bfrag[j][1] = f2tf32(bp[4 * BST]);
            }
            uint32_t afrag[2][4];
            ldmatrix_x4(afrag[0][0], afrag[0][1], afrag[0][2], afrag[0][3],
                        aAddr0 + ks * 8 * 4);
            ldmatrix_x4(afrag[1][0], afrag[1][1], afrag[1][2], afrag[1][3],
                        aAddr1 + ks * 8 * 4);
#pragma unroll
            for (int am = 0; am < 2; am++)
#pragma unroll
                for (int r = 0; r < 4; r++)
                    afrag[am][r] = f2tf32(__uint_as_float(afrag[am][r]));
#pragma unroll
            for (int am = 0; am < 2; am++)
#pragma unroll
                for (int j = 0; j < 7; j++)
                    mma1688(acc[am][j], afrag[am], bfrag[j]);
        }
    }

    // Epilogue: direct float2 stores (cols 2tg, 2tg+1 contiguous).
    float* Cb = out + (size_t)b * COUT * HW;
#pragma unroll
    for (int am = 0; am < 2; am++) {
        const int r0 = m0 + wm * 32 + am * 16 + g;
#pragma unroll
        for (int j = 0; j < 7; j++) {
            const int col = n0 + wn * 56 + j * 8 + 2 * tg;
            float2 v0 = make_float2(acc[am][j][0], acc[am][j][1]);
            float2 v1 = make_float2(acc[am][j][2], acc[am][j][3]);
            *reinterpret_cast<float2*>(Cb + (size_t)r0 * HW + col)       = v0;
            *reinterpret_cast<float2*>(Cb + (size_t)(r0 + 8) * HW + col) = v1;
        }
    }
}

extern "C" void kernel_launch(void* const* d_in, const int* in_sizes, int n_in,
                              void* d_out, int out_size)
{
    const float* input  = (const float*)d_in[0];  // (64, 512, 28, 28)
    const float* weight = (const float*)d_in[1];  // (64, 512, 512, 1, 1)
    const float* bias   = (const float*)d_in[2];  // (64, 512)
    float* out = (float*)d_out;

    cudaFuncSetAttribute(dynfc_tf32_kernel,
                         cudaFuncAttributeMaxDynamicSharedMemorySize,
                         SMEM_FLOATS * 4);
    dim3 grid(HW / BN, COUT / BM, 64);            // (7, 4, 64)
    dynfc_tf32_kernel<<<grid, 256, SMEM_FLOATS * 4>>>(input, weight, bias, out);
}